// round 10
// baseline (speedup 1.0000x reference)
#include <cuda_runtime.h>
#include <math.h>
#include <cstdint>

// One 16-CTA (nonportable) cluster, persistent, TWO cluster syncs per step.
// W1/W2 col-sliced, W2 also row-sliced, W3 replicated. Raw pre-activations
// (not activations) are exchanged; sigmoid applied replicated after sync.
// W1 update fused with next step's forward MV; W3 update deferred one step
// and fused with the a3 MV; o1 fused with W2-row update. Lazy-rescale
// normalization everywhere; b1/b2/b3 replicated with locally recomputed
// bit-identical scalars (o1 full vector exchanged for b1).

#define NC 16
#define T  512
#define Dd 1024
#define Hh 256
#define Oo 64
#define NSTEPS 1024
#define LRc 0.01f
#define EPSc 1e-8f
#define C1 16
#define TOTAL_OUT (Dd * Hh + Hh * Hh + Hh * Oo)   // 344064

// ---- SMEM layout (float offsets) ----
#define OFF_M1    0        // [C1][Dd] col-major W1 slice       16384
#define OFF_M2C   16384    // [C1][Hh] W2 col slice              4096
#define OFF_M2R   20480    // [C1][Hh] W2 row slice              4096
#define OFF_M3    24576    // [Oo][Hh] W3 full [j][i]           16384
#define OFF_X     40960    // [2][Dd]                            2048
#define OFF_TG    43008    // [2][Oo]                             128
#define OFF_ACC1  43136    // [Hh] raw l1 preact (pushed)         256
#define OFF_O1F   43392    // [Hh] o1 full (pushed)               256
#define OFF_ACC2  43648    // [Hh] raw l2 preact (pushed)         256
#define OFF_SPART 43904    // [NC][2] ss1,ss2 partials (pushed)    32
#define OFF_A1    43936    // [Hh]                                256
#define OFF_A2    44192    // [2][Hh]                             512
#define OFF_D3    44704    // [2][Oo]                             128
#define OFF_A3RAW 44832    // [Oo]                                 64
#define OFF_O2    44896    // [Hh]                                256
#define OFF_MB1   45152    // [Hh] replicated                     256
#define OFF_MB2   45408    // [Hh]                                256
#define OFF_MB3   45664    // [Oo]                                 64
#define OFF_STG1  45728    // [C1] staging                         16
#define OFF_O1OWN 45744    // [C1]                                 16
#define OFF_SRED  45760    // [16][3] ss3,ss1,ss2 per warp          48
#define OFF_SRB   45808    // [32] block_reduce scratch             32
#define OFF_SQ    45840    // q1,q2,q3,qb1,qb2,qb3                   8
#define SMEM_FLOATS 45848
#define SMEM_BYTES (SMEM_FLOATS * 4)

__device__ __forceinline__ uint32_t smem_u32(const void* p) {
    uint32_t a;
    asm("{ .reg .u64 t; cvta.to.shared.u64 t, %1; cvt.u32.u64 %0, t; }"
        : "=r"(a) : "l"(p));
    return a;
}
__device__ __forceinline__ void st_peer(uint32_t laddr, uint32_t rank, float v) {
    uint32_t r;
    asm volatile("mapa.shared::cluster.u32 %0, %1, %2;" : "=r"(r) : "r"(laddr), "r"(rank));
    asm volatile("st.shared::cluster.f32 [%0], %1;" :: "r"(r), "f"(v) : "memory");
}
#define CLUSTER_SYNC() do { \
    asm volatile("barrier.cluster.arrive.aligned;" ::: "memory"); \
    asm volatile("barrier.cluster.wait.aligned;" ::: "memory");   \
} while (0)

__device__ __forceinline__ float warp_sum(float v) {
    #pragma unroll
    for (int o = 16; o; o >>= 1) v += __shfl_xor_sync(0xffffffffu, v, o);
    return v;
}
__device__ __forceinline__ float block_reduce(float v, float* srb) {
    v = warp_sum(v);
    int w = threadIdx.x >> 5;
    if ((threadIdx.x & 31) == 0) srb[w] = v;
    __syncthreads();
    if (threadIdx.x < 32) {
        float t = (threadIdx.x < 16) ? srb[threadIdx.x] : 0.f;
        t = warp_sum(t);
        if (threadIdx.x == 0) srb[16] = t;
    }
    __syncthreads();
    float r = srb[16];
    __syncthreads();
    return r;
}
__device__ __forceinline__ float sigmoidf(float p) { return 1.f / (1.f + expf(-p)); }
__device__ __forceinline__ float sanitize(float v) { return isfinite(v) ? v : 0.f; }
__device__ __forceinline__ float dot4(float4 a, float4 b) {
    return a.x * b.x + a.y * b.y + a.z * b.z + a.w * b.w;
}

__global__ void __launch_bounds__(T, 1)
train_kernel(const float* __restrict__ X, const float* __restrict__ Tg,
             const float* __restrict__ W1g, const float* __restrict__ b1g,
             const float* __restrict__ W2g, const float* __restrict__ b2g,
             const float* __restrict__ W3g, const float* __restrict__ b3g,
             float* __restrict__ out, int out_size)
{
    extern __shared__ float sm[];
    float* m1    = sm + OFF_M1;
    float* m2c   = sm + OFF_M2C;
    float* m2r   = sm + OFF_M2R;
    float* m3    = sm + OFF_M3;
    float* xb    = sm + OFF_X;
    float* tgb   = sm + OFF_TG;
    float* acc1r = sm + OFF_ACC1;
    float* o1f   = sm + OFF_O1F;
    float* acc2r = sm + OFF_ACC2;
    float* spart = sm + OFF_SPART;
    float* a1f   = sm + OFF_A1;
    float* a2b   = sm + OFF_A2;
    float* d3b   = sm + OFF_D3;
    float* a3raw = sm + OFF_A3RAW;
    float* o2    = sm + OFF_O2;
    float* mb1   = sm + OFF_MB1;
    float* mb2   = sm + OFF_MB2;
    float* mb3   = sm + OFF_MB3;
    float* stg1  = sm + OFF_STG1;
    float* o1own = sm + OFF_O1OWN;
    float* sred  = sm + OFF_SRED;
    float* srb   = sm + OFF_SRB;
    float* sq    = sm + OFF_SQ;

    const int tid = threadIdx.x;
    const int w = tid >> 5, lane = tid & 31;

    uint32_t me;
    asm("mov.u32 %0, %%cluster_ctarank;" : "=r"(me));
    const uint32_t sbase = smem_u32(sm);
    const uint32_t ACC1A = sbase + OFF_ACC1 * 4;
    const uint32_t O1FA  = sbase + OFF_O1F * 4;
    const uint32_t ACC2A = sbase + OFF_ACC2 * 4;
    const uint32_t SPA   = sbase + OFF_SPART * 4;

    // ---- init ----
    for (int idx = tid; idx < C1 * Dd; idx += T) {
        int c = idx & 15, r = idx >> 4;
        m1[c * Dd + r] = W1g[r * Hh + me * C1 + c];
    }
    for (int idx = tid; idx < C1 * Hh; idx += T) {
        int c = idx & 15, i = idx >> 4;
        m2c[c * Hh + i] = W2g[i * Hh + me * C1 + c];
    }
    for (int idx = tid; idx < C1 * Hh; idx += T) {
        int r = idx >> 8, j = idx & 255;
        m2r[r * Hh + j] = W2g[(me * C1 + r) * Hh + j];
    }
    for (int idx = tid; idx < Oo * Hh; idx += T)
        m3[idx] = W3g[(idx & 255) * Oo + (idx >> 8)];
    if (tid < Hh) { mb1[tid] = b1g[tid]; mb2[tid] = b2g[tid]; o1f[tid] = 0.f; }
    if (tid < Oo) { mb3[tid] = b3g[tid]; d3b[Oo + tid] = 0.f; }
    if (tid < 8)  sq[tid] = 1.f;
    if (tid < 32) spart[tid] = 0.f;
    if (tid < 256) ((float4*)xb)[tid] = ((const float4*)X)[tid];
    else if (tid < 320) tgb[tid - 256] = Tg[tid - 256];
    __syncthreads();

    // acc1 for step 0
    {
        const float4* c4 = (const float4*)(m1 + w * Dd);
        const float4* x4 = (const float4*)xb;
        float acc = 0.f;
        #pragma unroll
        for (int k = 0; k < 8; k++) acc += dot4(c4[k * 32 + lane], x4[k * 32 + lane]);
        acc = warp_sum(acc);
        if (lane == 0) stg1[w] = acc;
    }
    __syncthreads();
    CLUSTER_SYNC();   // everyone's buffers ready before remote stores
    if (tid < 256) st_peer(ACC1A + ((me * C1 + (tid >> 4)) << 2), tid & 15, stg1[tid >> 4]);
    CLUSTER_SYNC();   // SYNC1 of step 0

    for (int step = 0; step < NSTEPS; ++step) {
        const int par = step & 1, pprev = par ^ 1;
        const float* xcur = xb + par * Dd;
        float* xnext = xb + pprev * Dd;
        float* a2c = a2b + par * Hh;
        const float* a2p = a2b + pprev * Hh;
        float* d3c = d3b + par * Oo;
        const float* d3p = d3b + pprev * Oo;

        // ---- scalars: q1, q2 from pushed partials ----
        if (step > 0 && tid < 2) {
            float s = 0.f;
            #pragma unroll
            for (int p = 0; p < NC; p++) s += spart[p * 2 + tid];
            sq[tid] = 1.f / fmaxf(sqrtf(s), EPSc);
        }
        __syncthreads();
        const float q1 = sq[0], q2 = sq[1], qb2 = sq[4];
        float qb1 = sq[3];

        // ---- b1 update (replicated; uses o1 of prev step) ----
        if (step > 0) {
            float bn1p = 0.f;
            if (tid < Hh) {
                float v = qb1 * mb1[tid] - LRc * o1f[tid];
                mb1[tid] = v; bn1p = v * v;
            }
            float bn1 = block_reduce(bn1p, srb);
            if (tid == 0) sq[3] = 1.f / fmaxf(sqrtf(bn1), EPSc);
            __syncthreads();
            qb1 = sq[3];
        }

        // ---- a1 full (replicated sigmoid over pushed raw accs) ----
        if (tid < Hh) a1f[tid] = sigmoidf(q1 * acc1r[tid] + qb1 * mb1[tid]);
        __syncthreads();

        // ---- MV layer 2 (own 16 cols), push raw ----
        {
            const float4* a14 = (const float4*)a1f;
            const float4* c4 = (const float4*)(m2c + w * Hh);
            float acc = 0.f;
            #pragma unroll
            for (int k = 0; k < 2; k++) acc += dot4(c4[k * 32 + lane], a14[k * 32 + lane]);
            acc = warp_sum(acc);
            if (lane == 0) stg1[w] = acc;
        }
        __syncthreads();
        if (tid < 256) st_peer(ACC2A + ((me * C1 + (tid >> 4)) << 2), tid & 15, stg1[tid >> 4]);
        CLUSTER_SYNC();   // SYNC2

        // ================= local region =================
        // prefetch next x / targets
        if (step + 1 < NSTEPS) {
            if (tid < 256)
                ((float4*)xnext)[tid] = ((const float4*)(X + (step + 1) * Dd))[tid];
            else if (tid < 320)
                tgb[pprev * Oo + (tid - 256)] = Tg[(step + 1) * Oo + (tid - 256)];
        }
        // a2 full (replicated)
        if (tid < Hh) a2c[tid] = sigmoidf(q2 * acc2r[tid] + qb2 * mb2[tid]);
        __syncthreads();

        // ---- fused: pending W3 update + a3 MV + ss3 ----
        {
            const float q3p = sq[2];
            float4* m34 = (float4*)m3;
            const float4* a2p4 = (const float4*)a2p;
            const float4* a2c4 = (const float4*)a2c;
            float ss3l = 0.f;
            #pragma unroll
            for (int s = 0; s < 4; s++) {
                int j = w + 16 * s;
                float dv = LRc * d3p[j];
                float acc3 = 0.f;
                #pragma unroll
                for (int k = 0; k < 2; k++) {
                    int ii = k * 32 + lane;
                    float4 wv = m34[j * 64 + ii], av = a2p4[ii];
                    wv.x = q3p * wv.x - dv * av.x;
                    wv.y = q3p * wv.y - dv * av.y;
                    wv.z = q3p * wv.z - dv * av.z;
                    wv.w = q3p * wv.w - dv * av.w;
                    m34[j * 64 + ii] = wv;
                    ss3l += dot4(wv, wv);
                    acc3 += dot4(wv, a2c4[ii]);
                }
                acc3 = warp_sum(acc3);
                if (lane == 0) a3raw[j] = acc3;
            }
            ss3l = warp_sum(ss3l);
            if (lane == 0) sred[w * 3] = ss3l;
        }
        __syncthreads();

        // ---- warp 0: q3, a3 sigmoid, softmax, d3, b3 update ----
        if (w == 0) {
            float s3 = (lane < 16) ? sred[lane * 3] : 0.f;
            s3 = warp_sum(s3);
            float q3u = (step == 0) ? 1.f : 1.f / fmaxf(sqrtf(s3), EPSc);
            float qb3 = sq[5];
            float a30 = sigmoidf(q3u * a3raw[lane] + qb3 * mb3[lane]);
            float a31 = sigmoidf(q3u * a3raw[lane + 32] + qb3 * mb3[lane + 32]);
            const float* tgc = tgb + par * Oo;
            float t0 = tgc[lane], t1 = tgc[lane + 32];
            float m = fmaxf(-a30, -a31);
            #pragma unroll
            for (int o = 16; o; o >>= 1) m = fmaxf(m, __shfl_xor_sync(0xffffffffu, m, o));
            float e0 = expf(-a30 - m), e1 = expf(-a31 - m);
            float s = warp_sum(e0 + e1);
            float inv = 1.f / s;
            float d30 = (t0 - e0 * inv) * a30 * (1.f - a30);
            float d31 = (t1 - e1 * inv) * a31 * (1.f - a31);
            d3c[lane] = d30; d3c[lane + 32] = d31;
            float v0 = qb3 * mb3[lane] - LRc * d30;
            float v1 = qb3 * mb3[lane + 32] - LRc * d31;
            mb3[lane] = v0; mb3[lane + 32] = v1;
            float bn3 = warp_sum(v0 * v0 + v1 * v1);
            if (lane == 0) {
                sq[2] = q3u;
                sq[5] = 1.f / fmaxf(sqrtf(bn3), EPSc);
            }
        }
        __syncthreads();
        const float q3u = sq[2];

        // ---- o2 (uses post-(t-1) W3 = current m3) ----
        if (tid < Hh) {
            float raw = 0.f;
            #pragma unroll 16
            for (int j = 0; j < Oo; j++) raw += m3[j * Hh + tid] * d3c[j];
            float a = a2c[tid];
            o2[tid] = q3u * raw * a * (1.f - a);
        }
        __syncthreads();

        // ---- fused: o1 (own rows) + W2 row update ----
        float ovw;
        {
            float a1w = a1f[me * C1 + w];
            float sva = LRc * a1w;
            float4* r4 = (float4*)(m2r + w * Hh);
            const float4* o24 = (const float4*)o2;
            float acc = 0.f;
            #pragma unroll
            for (int k = 0; k < 2; k++) {
                int ii = k * 32 + lane;
                float4 rv = r4[ii], ov4 = o24[ii];
                acc += dot4(rv, ov4);
                rv.x = q2 * rv.x - sva * ov4.x;
                rv.y = q2 * rv.y - sva * ov4.y;
                rv.z = q2 * rv.z - sva * ov4.z;
                rv.w = q2 * rv.w - sva * ov4.w;
                r4[ii] = rv;
            }
            acc = warp_sum(acc);
            ovw = q2 * acc * a1w * (1.f - a1w);
            if (lane == 0) o1own[w] = ovw;
        }

        // ---- fused: W1 update + next-step forward MV + ss1 ----
        {
            float sv = LRc * ovw;
            float4* c4 = (float4*)(m1 + w * Dd);
            const float4* xc4 = (const float4*)xcur;
            const float4* xn4 = (const float4*)xnext;
            float ss1l = 0.f, accn = 0.f;
            #pragma unroll
            for (int k = 0; k < 8; k++) {
                int ii = k * 32 + lane;
                float4 wv = c4[ii], xv = xc4[ii];
                wv.x = q1 * wv.x - sv * xv.x;
                wv.y = q1 * wv.y - sv * xv.y;
                wv.z = q1 * wv.z - sv * xv.z;
                wv.w = q1 * wv.w - sv * xv.w;
                c4[ii] = wv;
                ss1l += dot4(wv, wv);
                accn += dot4(wv, xn4[ii]);
            }
            ss1l = warp_sum(ss1l);
            accn = warp_sum(accn);
            if (lane == 0) { stg1[w] = accn; sred[w * 3 + 1] = ss1l; }
        }

        // ---- W2 col update + ss2 ----
        {
            float sv = LRc * o2[me * C1 + w];
            float4* c4 = (float4*)(m2c + w * Hh);
            const float4* a14 = (const float4*)a1f;
            float ss2l = 0.f;
            #pragma unroll
            for (int k = 0; k < 2; k++) {
                int ii = k * 32 + lane;
                float4 wv = c4[ii], av = a14[ii];
                wv.x = q2 * wv.x - sv * av.x;
                wv.y = q2 * wv.y - sv * av.y;
                wv.z = q2 * wv.z - sv * av.z;
                wv.w = q2 * wv.w - sv * av.w;
                c4[ii] = wv;
                ss2l += dot4(wv, wv);
            }
            ss2l = warp_sum(ss2l);
            if (lane == 0) sred[w * 3 + 2] = ss2l;
        }

        // ---- b2 update (replicated) ----
        {
            float bn2p = 0.f;
            if (tid < Hh) {
                float v = qb2 * mb2[tid] - LRc * o2[tid];
                mb2[tid] = v; bn2p = v * v;
            }
            float bn2 = block_reduce(bn2p, srb);
            if (tid == 0) sq[4] = 1.f / fmaxf(sqrtf(bn2), EPSc);
        }
        __syncthreads();

        // ---- end-of-step pushes: acc1(next), o1 full, ss1/ss2 partials ----
        if (tid < 256) {
            st_peer(ACC1A + ((me * C1 + (tid >> 4)) << 2), tid & 15, stg1[tid >> 4]);
        } else {
            int t2 = tid - 256;
            st_peer(O1FA + ((me * C1 + (t2 >> 4)) << 2), t2 & 15, o1own[t2 >> 4]);
        }
        if (w == 1) {
            float v = (lane < 16) ? sred[lane * 3 + 1] : 0.f;
            v = warp_sum(v);
            if (lane < 16) st_peer(SPA + ((me * 2 + 0) << 2), lane, v);
        }
        if (w == 2) {
            float v = (lane < 16) ? sred[lane * 3 + 2] : 0.f;
            v = warp_sum(v);
            if (lane < 16) st_peer(SPA + ((me * 2 + 1) << 2), lane, v);
        }
        CLUSTER_SYNC();   // SYNC1 of next step
    }

    // ---- post-loop: final q1/q2, apply pending W3 update ----
    if (tid < 2) {
        float s = 0.f;
        #pragma unroll
        for (int p = 0; p < NC; p++) s += spart[p * 2 + tid];
        sq[tid] = 1.f / fmaxf(sqrtf(s), EPSc);
    }
    __syncthreads();
    {
        const float q3p = sq[2];
        const int lpar = (NSTEPS - 1) & 1;
        const float* a2p = a2b + lpar * Hh;
        const float* d3p = d3b + lpar * Oo;
        float4* m34 = (float4*)m3;
        const float4* a2p4 = (const float4*)a2p;
        float ss3l = 0.f;
        #pragma unroll
        for (int k = 0; k < 8; k++) {
            int e4 = tid + 512 * k;
            int j = e4 >> 6, i4 = e4 & 63;
            float dv = LRc * d3p[j];
            float4 wv = m34[e4], av = a2p4[i4];
            wv.x = q3p * wv.x - dv * av.x;
            wv.y = q3p * wv.y - dv * av.y;
            wv.z = q3p * wv.z - dv * av.z;
            wv.w = q3p * wv.w - dv * av.w;
            m34[e4] = wv;
            ss3l += dot4(wv, wv);
        }
        float ss3 = block_reduce(ss3l, srb);
        if (tid == 0) sq[2] = 1.f / fmaxf(sqrtf(ss3), EPSc);
    }
    __syncthreads();
    const float q1f = sq[0], q2f = sq[1], q3f = sq[2];

    // ---- write out: W1 | W2 | W3 (row-major), guarded, sanitized ----
    for (int idx = tid; idx < C1 * Dd; idx += T) {
        int c = idx & 15, r = idx >> 4;
        int o = r * Hh + me * C1 + c;
        if (o < out_size) out[o] = sanitize(q1f * m1[c * Dd + r]);
    }
    for (int idx = tid; idx < C1 * Hh; idx += T) {
        int c = idx & 15, i = idx >> 4;
        int o = Dd * Hh + i * Hh + me * C1 + c;
        if (o < out_size) out[o] = sanitize(q2f * m2c[c * Hh + i]);
    }
    for (int idx = tid; idx < 4 * Hh; idx += T) {
        int j = (int)me * 4 + (idx & 3), i = idx >> 2;
        int o = Dd * Hh + Hh * Hh + i * Oo + j;
        if (o < out_size) out[o] = sanitize(q3f * m3[j * Hh + i]);
    }
    for (int o = TOTAL_OUT + (int)me * T + tid; o < out_size; o += NC * T) out[o] = 0.f;
}

extern "C" void kernel_launch(void* const* d_in, const int* in_sizes, int n_in,
                              void* d_out, int out_size) {
    const float* X = 0; const float* Tg = 0;
    const float* W1 = 0; const float* b1 = 0;
    const float* W2 = 0; const float* b2 = 0;
    const float* W3 = 0; const float* b3 = 0;
    for (int i = 0; i < n_in; i++) {
        const float* p = (const float*)d_in[i];
        switch (in_sizes[i]) {
            case 1024 * 1024: X = p; break;
            case 1024 * 256:  W1 = p; break;
            case 256 * 256:   if (!Tg) Tg = p; else W2 = p; break;
            case 256 * 64:    W3 = p; break;
            case 256:         if (!b1) b1 = p; else b2 = p; break;
            case 64:          b3 = p; break;
            default: break;
        }
    }
    cudaFuncSetAttribute(train_kernel, cudaFuncAttributeMaxDynamicSharedMemorySize, SMEM_BYTES);
    cudaFuncSetAttribute(train_kernel, cudaFuncAttributeNonPortableClusterSizeAllowed, 1);

    cudaLaunchConfig_t cfg = {};
    cfg.gridDim = dim3(NC, 1, 1);
    cfg.blockDim = dim3(T, 1, 1);
    cfg.dynamicSmemBytes = SMEM_BYTES;
    cudaLaunchAttribute attrs[1];
    attrs[0].id = cudaLaunchAttributeClusterDimension;
    attrs[0].val.clusterDim.x = NC;
    attrs[0].val.clusterDim.y = 1;
    attrs[0].val.clusterDim.z = 1;
    cfg.attrs = attrs;
    cfg.numAttrs = 1;
    cudaLaunchKernelEx(&cfg, train_kernel, X, Tg, W1, b1, W2, b2, W3, b3,
                       (float*)d_out, out_size);
}